// round 4
// baseline (speedup 1.0000x reference)
#include <cuda_runtime.h>

#define HID 128
#define INP 33
#define OUTD 3
#define TT 2000
#define BATCH 256

typedef unsigned long long u64;

// Packed fp32x2 FMA: 2 FMAs per issue slot (ptxas never auto-fuses this; PTX only).
__device__ __forceinline__ u64 ffma2(u64 a, u64 b, u64 c) {
    u64 d;
    asm("fma.rn.f32x2 %0, %1, %2, %3;" : "=l"(d) : "l"(a), "l"(b), "l"(c));
    return d;
}
__device__ __forceinline__ float2 unpack2(u64 v) {
    float2 f;
    asm("mov.b64 {%0, %1}, %2;" : "=f"(f.x), "=f"(f.y) : "l"(v));
    return f;
}
__device__ __forceinline__ u64 pack2(float x, float y) {
    u64 v;
    asm("mov.b64 %0, {%1, %2};" : "=l"(v) : "f"(x), "f"(y));
    return v;
}

// Accurate-enough tanh (rel err ~1e-6 via __expf, avoids 6e-4-error tanh.approx
// that --use_fast_math could substitute for tanhf).
__device__ __forceinline__ float fast_tanh(float x) {
    float ax = fabsf(x);
    float e = __expf(2.0f * fminf(ax, 10.0f));   // exp(20) finite; t rounds to 1 beyond
    float t = 1.0f - 2.0f / (e + 1.0f);
    return copysignf(t, x);
}

// One CTA per batch row; thread j owns hidden unit j. W_rec row j lives in
// 128 registers (zero smem traffic for weights); h broadcast from smem,
// double-buffered -> ONE __syncthreads per timestep. x[t+1] prefetched during
// step t (L2-resident after first pass; graph replay keeps it hot).
__global__ void __launch_bounds__(128, 2)
rnn_recurrence_kernel(const float* __restrict__ x,
                      const float* __restrict__ W_in,
                      const float* __restrict__ b_in,
                      const float* __restrict__ W_rec,
                      float* __restrict__ hidden)
{
    __shared__ __align__(16) float hbuf[2][HID];
    __shared__ __align__(16) float xbuf[2][40];

    const int j = threadIdx.x;      // hidden unit
    const int b = blockIdx.x;       // batch row

    // --- Load W_rec row j into registers as packed f32x2 pairs (128 regs) ---
    u64 w[64];
    {
        const ulonglong2* wrow = (const ulonglong2*)(W_rec + j * HID); // 512B-aligned
        #pragma unroll
        for (int k = 0; k < 32; k++) {
            ulonglong2 v = wrow[k];
            w[2 * k]     = v.x;
            w[2 * k + 1] = v.y;
        }
    }

    // --- Load W_in row j (33 floats, only 4B-aligned) and pack 16 pairs ---
    u64 wi2[16];
    float wi_last;
    {
        float win[INP];
        #pragma unroll
        for (int i = 0; i < INP; i++) win[i] = W_in[j * INP + i];
        #pragma unroll
        for (int i = 0; i < 16; i++) wi2[i] = pack2(win[2 * i], win[2 * i + 1]);
        wi_last = win[32];
    }
    const float bj = b_in[j];

    // --- Init state ---
    hbuf[0][j] = 0.0f;
    const float* xb = x + (size_t)b * TT * INP;
    if (j < INP) xbuf[0][j] = xb[j];
    float hj = 0.0f;                      // own h value stays in a register
    float* hout = hidden + (size_t)b * TT * HID + j;

    __syncthreads();

    int p = 0;
    for (int t = 0; t < TT; t++) {
        // Prefetch next x row early (latency hidden under this step's compute)
        float xn = 0.0f;
        if (j < INP && t + 1 < TT) xn = __ldg(xb + (t + 1) * INP + j);

        const u64*        xs = (const u64*)xbuf[p];
        const ulonglong2* hs = (const ulonglong2*)hbuf[p];

        u64 acc[4] = {0ull, 0ull, 0ull, 0ull};

        // Input projection: 16 packed FMAs over x[0..31]
        #pragma unroll
        for (int i = 0; i < 16; i++)
            acc[i & 3] = ffma2(wi2[i], xs[i], acc[i & 3]);

        // Recurrent matvec: 64 packed FMAs, h via broadcast LDS.128
        #pragma unroll
        for (int k = 0; k < 32; k++) {
            ulonglong2 hh = hs[k];
            acc[(2 * k)     & 3] = ffma2(w[2 * k],     hh.x, acc[(2 * k)     & 3]);
            acc[(2 * k + 1) & 3] = ffma2(w[2 * k + 1], hh.y, acc[(2 * k + 1) & 3]);
        }

        float2 f0 = unpack2(acc[0]), f1 = unpack2(acc[1]);
        float2 f2 = unpack2(acc[2]), f3 = unpack2(acc[3]);
        float pre = ((f0.x + f1.x) + (f2.x + f3.x))
                  + ((f0.y + f1.y) + (f2.y + f3.y))
                  + bj + wi_last * xbuf[p][32];

        float hn = 0.96f * hj + 0.04f * fast_tanh(pre);

        hout[t * HID] = hn;               // coalesced 512B store per (b,t)
        hbuf[p ^ 1][j] = hn;              // write the OTHER buffer
        if (j < INP) xbuf[p ^ 1][j] = xn;
        hj = hn;

        __syncthreads();                  // single barrier per step
        p ^= 1;
    }
}

// Bandwidth-bound readout: one warp per (b,t) row, coalesced float4 loads,
// 3 shuffle-reduced dot products.
__global__ void readout_kernel(const float* __restrict__ hidden,
                               const float* __restrict__ W_out,
                               const float* __restrict__ b_out,
                               float* __restrict__ pred,
                               int nrows)
{
    int gwarp = (blockIdx.x * blockDim.x + threadIdx.x) >> 5;
    int lane  = threadIdx.x & 31;
    if (gwarp >= nrows) return;

    const float4* h4 = (const float4*)(hidden + (size_t)gwarp * HID);
    float4 hv = h4[lane];

    const float4* w4 = (const float4*)W_out;     // rows are 512B apart
    float4 w0 = __ldg(&w4[lane]);
    float4 w1 = __ldg(&w4[32 + lane]);
    float4 w2 = __ldg(&w4[64 + lane]);

    float p0 = hv.x * w0.x + hv.y * w0.y + hv.z * w0.z + hv.w * w0.w;
    float p1 = hv.x * w1.x + hv.y * w1.y + hv.z * w1.z + hv.w * w1.w;
    float p2 = hv.x * w2.x + hv.y * w2.y + hv.z * w2.z + hv.w * w2.w;

    #pragma unroll
    for (int off = 16; off > 0; off >>= 1) {
        p0 += __shfl_xor_sync(0xFFFFFFFFu, p0, off);
        p1 += __shfl_xor_sync(0xFFFFFFFFu, p1, off);
        p2 += __shfl_xor_sync(0xFFFFFFFFu, p2, off);
    }

    if (lane == 0) {
        float* o = pred + (size_t)gwarp * OUTD;
        o[0] = p0 + b_out[0];
        o[1] = p1 + b_out[1];
        o[2] = p2 + b_out[2];
    }
}

extern "C" void kernel_launch(void* const* d_in, const int* in_sizes, int n_in,
                              void* d_out, int out_size)
{
    const float* x     = (const float*)d_in[0];  // [B,T,33]
    const float* W_in  = (const float*)d_in[1];  // [128,33]
    const float* b_in  = (const float*)d_in[2];  // [128]
    const float* W_rec = (const float*)d_in[3];  // [128,128]
    const float* W_out = (const float*)d_in[4];  // [3,128]
    const float* b_out = (const float*)d_in[5];  // [3]

    float* out    = (float*)d_out;
    float* pred   = out;                                   // [B,T,3] first
    float* hidden = out + (size_t)BATCH * TT * OUTD;       // then [B,T,128]

    rnn_recurrence_kernel<<<BATCH, 128>>>(x, W_in, b_in, W_rec, hidden);

    int nrows = BATCH * TT;                                // 512000
    int warps_per_block = 8;                               // 256 threads
    int blocks = (nrows + warps_per_block - 1) / warps_per_block;
    readout_kernel<<<blocks, 256>>>(hidden, W_out, b_out, pred, nrows);
}

// round 5
// speedup vs baseline: 1.2428x; 1.2428x over previous
#include <cuda_runtime.h>

#define HID 128
#define INP 33
#define OUTD 3
#define TT 2000
#define BATCH 256

typedef unsigned long long u64;

// Packed fp32x2 FMA (FFMA2) — only reachable via PTX fma.rn.f32x2.
__device__ __forceinline__ u64 ffma2(u64 a, u64 b, u64 c) {
    u64 d;
    asm("fma.rn.f32x2 %0, %1, %2, %3;" : "=l"(d) : "l"(a), "l"(b), "l"(c));
    return d;
}
__device__ __forceinline__ float2 unpack2(u64 v) {
    float2 f;
    asm("mov.b64 {%0, %1}, %2;" : "=f"(f.x), "=f"(f.y) : "l"(v));
    return f;
}
__device__ __forceinline__ u64 pack2(float x, float y) {
    u64 v;
    asm("mov.b64 %0, {%1, %2};" : "=l"(v) : "f"(x), "f"(y));
    return v;
}

// Accurate tanh via __expf (MUFU ex2): rel err ~1e-6, safe for the 2000-step
// recurrence (tanh.approx's 6e-4 abs error is not).
__device__ __forceinline__ float fast_tanh(float x) {
    float ax = fabsf(x);
    float e = __expf(2.0f * fminf(ax, 10.0f));
    float t = 1.0f - 2.0f / (e + 1.0f);
    return copysignf(t, x);
}

// ---------------------------------------------------------------------------
// Pass 1: input projection, written IN-PLACE into the hidden output buffer.
// proj[row, j] = b_in[j] + sum_i x[row, i] * W_in[j, i]
// Each CTA: 128 threads (thread j holds W_in row j in 17 packed regs),
// processes 16 (b,t) rows staged in smem (rows padded to 34 floats so the
// packed pairs stay 8B-aligned and the pad pairs multiply by zero).
// ---------------------------------------------------------------------------
#define PROJ_ROWS 16

__global__ void __launch_bounds__(128)
proj_kernel(const float* __restrict__ x,
            const float* __restrict__ W_in,
            const float* __restrict__ b_in,
            float* __restrict__ proj)
{
    __shared__ __align__(16) float xs[PROJ_ROWS][34];

    const int tid = threadIdx.x;
    const long base_row = (long)blockIdx.x * PROJ_ROWS;

    // W_in row tid -> 17 packed pairs (last pair = (w32, 0))
    u64 wi[17];
    {
        float wv[34];
        #pragma unroll
        for (int i = 0; i < INP; i++) wv[i] = W_in[tid * INP + i];
        wv[33] = 0.0f;
        #pragma unroll
        for (int i = 0; i < 17; i++) wi[i] = pack2(wv[2 * i], wv[2 * i + 1]);
    }
    const float bj = b_in[tid];

    // Stage 16 rows of x, coalesced; zero the pad column.
    const float* xsrc = x + base_row * INP;
    for (int idx = tid; idx < PROJ_ROWS * INP; idx += 128) {
        int r = idx / INP, i = idx - r * INP;
        xs[r][i] = xsrc[idx];
    }
    if (tid < PROJ_ROWS) xs[tid][33] = 0.0f;
    __syncthreads();

    #pragma unroll 4
    for (int r = 0; r < PROJ_ROWS; r++) {
        const u64* xp = (const u64*)xs[r];   // 34-float rows: 8B-aligned pairs
        u64 acc[4] = {0ull, 0ull, 0ull, 0ull};
        #pragma unroll
        for (int i = 0; i < 17; i++)
            acc[i & 3] = ffma2(wi[i], xp[i], acc[i & 3]);
        float2 f0 = unpack2(acc[0]), f1 = unpack2(acc[1]);
        float2 f2 = unpack2(acc[2]), f3 = unpack2(acc[3]);
        float s = ((f0.x + f1.x) + (f2.x + f3.x))
                + ((f0.y + f1.y) + (f2.y + f3.y)) + bj;
        proj[(base_row + r) * HID + tid] = s;   // coalesced 512B store
    }
}

// ---------------------------------------------------------------------------
// Pass 2: the serial recurrence. One CTA per batch row; thread j owns hidden
// unit j and W_rec row j in 128 registers (no input-weight regs anymore ->
// ~155 regs total, no spills). h broadcast via double-buffered smem, ONE
// __syncthreads per step. proj[t] is consumed from the hidden buffer and
// overwritten with h[t] by the same thread; proj prefetched 2 steps ahead
// (one coalesced LDG.32 per thread) to hide DRAM latency.
// ---------------------------------------------------------------------------
__global__ void __launch_bounds__(128, 2)
rnn_recurrence_kernel(const float* __restrict__ W_rec,
                      float* __restrict__ hidden /* in: proj, out: h */)
{
    __shared__ __align__(16) float hbuf[2][HID];

    const int j = threadIdx.x;
    const int b = blockIdx.x;

    // W_rec row j as 64 packed pairs (rows are 512B-aligned).
    u64 w[64];
    {
        const ulonglong2* wrow = (const ulonglong2*)(W_rec + j * HID);
        #pragma unroll
        for (int k = 0; k < 32; k++) {
            ulonglong2 v = wrow[k];
            w[2 * k]     = v.x;
            w[2 * k + 1] = v.y;
        }
    }

    hbuf[0][j] = 0.0f;
    float hj = 0.0f;
    float* pj = hidden + (size_t)b * TT * HID + j;

    // Prefetch pipeline, distance 2.
    float p_cur = __ldg(pj);
    float p_nxt = __ldg(pj + HID);
    __syncthreads();

    int p = 0;
    for (int t = 0; t < TT; t++) {
        float p_fut = 0.0f;
        if (t + 2 < TT) p_fut = __ldg(pj + (size_t)(t + 2) * HID);

        const ulonglong2* hs = (const ulonglong2*)hbuf[p];
        u64 acc[4] = {0ull, 0ull, 0ull, 0ull};

        #pragma unroll
        for (int k = 0; k < 32; k++) {
            ulonglong2 hh = hs[k];                       // broadcast LDS.128
            acc[(2 * k)     & 3] = ffma2(w[2 * k],     hh.x, acc[(2 * k)     & 3]);
            acc[(2 * k + 1) & 3] = ffma2(w[2 * k + 1], hh.y, acc[(2 * k + 1) & 3]);
        }

        float2 f0 = unpack2(acc[0]), f1 = unpack2(acc[1]);
        float2 f2 = unpack2(acc[2]), f3 = unpack2(acc[3]);
        float pre = ((f0.x + f1.x) + (f2.x + f3.x))
                  + ((f0.y + f1.y) + (f2.y + f3.y)) + p_cur;

        float hn = 0.96f * hj + 0.04f * fast_tanh(pre);

        pj[(size_t)t * HID] = hn;     // overwrite consumed proj slot, coalesced
        hbuf[p ^ 1][j] = hn;
        hj = hn;
        p_cur = p_nxt;
        p_nxt = p_fut;

        __syncthreads();              // single barrier per step
        p ^= 1;
    }
}

// ---------------------------------------------------------------------------
// Pass 3: readout. One warp per (b,t) row, coalesced float4 loads of h,
// W_out from L1, 3 butterfly-reduced dot products.
// ---------------------------------------------------------------------------
__global__ void readout_kernel(const float* __restrict__ hidden,
                               const float* __restrict__ W_out,
                               const float* __restrict__ b_out,
                               float* __restrict__ pred,
                               int nrows)
{
    int gwarp = (blockIdx.x * blockDim.x + threadIdx.x) >> 5;
    int lane  = threadIdx.x & 31;
    if (gwarp >= nrows) return;

    const float4* h4 = (const float4*)(hidden + (size_t)gwarp * HID);
    float4 hv = h4[lane];

    const float4* w4 = (const float4*)W_out;
    float4 w0 = __ldg(&w4[lane]);
    float4 w1 = __ldg(&w4[32 + lane]);
    float4 w2 = __ldg(&w4[64 + lane]);

    float p0 = hv.x * w0.x + hv.y * w0.y + hv.z * w0.z + hv.w * w0.w;
    float p1 = hv.x * w1.x + hv.y * w1.y + hv.z * w1.z + hv.w * w1.w;
    float p2 = hv.x * w2.x + hv.y * w2.y + hv.z * w2.z + hv.w * w2.w;

    #pragma unroll
    for (int off = 16; off > 0; off >>= 1) {
        p0 += __shfl_xor_sync(0xFFFFFFFFu, p0, off);
        p1 += __shfl_xor_sync(0xFFFFFFFFu, p1, off);
        p2 += __shfl_xor_sync(0xFFFFFFFFu, p2, off);
    }

    if (lane == 0) {
        float* o = pred + (size_t)gwarp * OUTD;
        o[0] = p0 + b_out[0];
        o[1] = p1 + b_out[1];
        o[2] = p2 + b_out[2];
    }
}

extern "C" void kernel_launch(void* const* d_in, const int* in_sizes, int n_in,
                              void* d_out, int out_size)
{
    const float* x     = (const float*)d_in[0];  // [B,T,33]
    const float* W_in  = (const float*)d_in[1];  // [128,33]
    const float* b_in  = (const float*)d_in[2];  // [128]
    const float* W_rec = (const float*)d_in[3];  // [128,128]
    const float* W_out = (const float*)d_in[4];  // [3,128]
    const float* b_out = (const float*)d_in[5];  // [3]

    float* out    = (float*)d_out;
    float* pred   = out;                               // [B,T,3]
    float* hidden = out + (size_t)BATCH * TT * OUTD;   // [B,T,128]; proj then h

    // Pass 1: proj -> hidden (in place)
    int nrows = BATCH * TT;                            // 512000 (divisible by 16)
    proj_kernel<<<nrows / PROJ_ROWS, 128>>>(x, W_in, b_in, hidden);

    // Pass 2: serial recurrence (reads proj, overwrites with h)
    rnn_recurrence_kernel<<<BATCH, 128>>>(W_rec, hidden);

    // Pass 3: readout
    int blocks = (nrows + 7) / 8;                      // 8 warps (256 thr) / block
    readout_kernel<<<blocks, 256>>>(hidden, W_out, b_out, pred, nrows);
}